// round 3
// baseline (speedup 1.0000x reference)
#include <cuda_runtime.h>
#include <cstdint>

#define B_     32
#define H_     2048
#define V_     128000
#define HIST_  2048
#define KCH    256
#define VTILE  32
#define CAP    1024

// ---------------- device scratch (no allocation allowed) ----------------
__device__ unsigned long long g_h2[16 * H_];                 // b-paired layernorm output
__device__ float              g_logits[(size_t)B_ * V_];     // 16.4 MB
__device__ float              g_pen[B_ * HIST_];

// ---------------- f32x2 helpers ----------------
__device__ __forceinline__ unsigned long long fma2(unsigned long long a,
                                                   unsigned long long b,
                                                   unsigned long long c) {
    unsigned long long d;
    asm("fma.rn.f32x2 %0, %1, %2, %3;" : "=l"(d) : "l"(a), "l"(b), "l"(c));
    return d;
}
__device__ __forceinline__ unsigned long long add2(unsigned long long a,
                                                   unsigned long long b) {
    unsigned long long d;
    asm("add.rn.f32x2 %0, %1, %2;" : "=l"(d) : "l"(a), "l"(b));
    return d;
}
__device__ __forceinline__ unsigned long long dup2(float x) {
    unsigned long long d;
    asm("mov.b64 %0, {%1, %1};" : "=l"(d) : "f"(x));
    return d;
}

// ---------------- K0: LayerNorm, write b-paired h2 ----------------
__global__ void __launch_bounds__(256) ln_kernel(const float* __restrict__ hs,
                                                 const float* __restrict__ gamma,
                                                 const float* __restrict__ beta) {
    __shared__ float sbuf[8];
    const int b = blockIdx.x, tid = threadIdx.x;
    const float* x = hs + (size_t)b * H_;

    float v[8];
#pragma unroll
    for (int i = 0; i < 8; i++) v[i] = x[i * 256 + tid];

    float s = 0.f;
#pragma unroll
    for (int i = 0; i < 8; i++) s += v[i];
#pragma unroll
    for (int off = 16; off >= 1; off >>= 1) s += __shfl_xor_sync(0xffffffffu, s, off);
    if ((tid & 31) == 0) sbuf[tid >> 5] = s;
    __syncthreads();
    if (tid == 0) {
        float t = 0.f;
        for (int i = 0; i < 8; i++) t += sbuf[i];
        sbuf[0] = t * (1.0f / H_);
    }
    __syncthreads();
    const float mean = sbuf[0];
    __syncthreads();

    float sq = 0.f;
#pragma unroll
    for (int i = 0; i < 8; i++) { float d = v[i] - mean; sq += d * d; }
#pragma unroll
    for (int off = 16; off >= 1; off >>= 1) sq += __shfl_xor_sync(0xffffffffu, sq, off);
    if ((tid & 31) == 0) sbuf[tid >> 5] = sq;
    __syncthreads();
    if (tid == 0) {
        float t = 0.f;
        for (int i = 0; i < 8; i++) t += sbuf[i];
        sbuf[0] = t * (1.0f / H_);
    }
    __syncthreads();
    const float var = sbuf[0];
    const float rs = rsqrtf(var + 1e-5f);

    float* gf = reinterpret_cast<float*>(g_h2);
    const int pr = b >> 1, lo = b & 1;
#pragma unroll
    for (int i = 0; i < 8; i++) {
        const int k = i * 256 + tid;
        const float h = (v[i] - mean) * rs * gamma[k] + beta[k];
        gf[((size_t)pr * H_ + k) * 2 + lo] = h;
    }
}

// ---------------- K1: fp32 GEMM via packed FFMA2, lanes span K ----------------
__global__ void __launch_bounds__(512, 1) gemm_kernel(const float* __restrict__ W) {
    __shared__ __align__(16) unsigned long long sh2[16 * KCH];
    const int tid  = threadIdx.x;
    const int lane = tid & 31;
    const int wrp  = tid >> 5;
    const int pg   = wrp & 3;       // pair-group: pairs pg*4 .. pg*4+3  (b = 2P, 2P+1)
    const int vg   = wrp >> 2;      // v-group: 8 rows
    const int vblk = blockIdx.x * VTILE;
    const int v0   = vblk + vg * 8;

    unsigned long long acc[4][8];
#pragma unroll
    for (int p = 0; p < 4; p++)
#pragma unroll
        for (int q = 0; q < 8; q++) acc[p][q] = 0ull;

    for (int c = 0; c < H_; c += KCH) {
        __syncthreads();
        for (int idx = tid; idx < 16 * KCH; idx += 512) {
            const int p  = idx >> 8;            // KCH == 256
            const int kk = idx & (KCH - 1);
            sh2[idx] = g_h2[p * H_ + c + kk];
        }
        __syncthreads();

#pragma unroll
        for (int j = 0; j < KCH / 64; j++) {
            const int kl = lane * 2 + j * 64;   // lane-private k within chunk
            ulonglong2 hv[4];
#pragma unroll
            for (int p = 0; p < 4; p++)
                hv[p] = *reinterpret_cast<const ulonglong2*>(&sh2[(pg * 4 + p) * KCH + kl]);

            const float* wp = W + (size_t)v0 * H_ + (c + kl);
            float2 wv[8];
#pragma unroll
            for (int q = 0; q < 8; q++)
                wv[q] = *reinterpret_cast<const float2*>(wp + (size_t)q * H_);

#pragma unroll
            for (int q = 0; q < 8; q++) {
                const unsigned long long a0 = dup2(wv[q].x);
                const unsigned long long a1 = dup2(wv[q].y);
#pragma unroll
                for (int p = 0; p < 4; p++) {
                    acc[p][q] = fma2(a0, hv[p].x, acc[p][q]);
                    acc[p][q] = fma2(a1, hv[p].y, acc[p][q]);
                }
            }
        }
    }

    // cross-lane (k) reduction: every lane ends with the full sum
#pragma unroll
    for (int p = 0; p < 4; p++)
#pragma unroll
        for (int q = 0; q < 8; q++)
#pragma unroll
            for (int off = 16; off >= 1; off >>= 1)
                acc[p][q] = add2(acc[p][q], __shfl_xor_sync(0xffffffffu, acc[p][q], off));

    // lane (p*8+q) owns output (pair p, v q)
    unsigned long long mine = 0ull;
#pragma unroll
    for (int p = 0; p < 4; p++)
#pragma unroll
        for (int q = 0; q < 8; q++)
            if (lane == p * 8 + q) mine = acc[p][q];

    const int P = pg * 4 + (lane >> 3);
    const int v = vblk + vg * 8 + (lane & 7);
    const float f0 = __uint_as_float((unsigned)(mine & 0xffffffffu));
    const float f1 = __uint_as_float((unsigned)(mine >> 32));
    g_logits[(size_t)(2 * P)     * V_ + v] = f0;
    g_logits[(size_t)(2 * P + 1) * V_ + v] = f1;
}

// ---------------- P1/P2: repetition penalty (two-phase, race-free) ----------------
// NOTE: input_ids is int32 on device (JAX x64 disabled downcasts int64->int32).
__global__ void __launch_bounds__(256) pen_gather(const int* __restrict__ ids) {
    const int t = blockIdx.x * 256 + threadIdx.x;
    if (t >= B_ * HIST_) return;
    const int b = t >> 11;
    const int v = ids[t];
    if ((unsigned)v >= (unsigned)V_) return;     // hard guard against dtype surprises
    const float g = g_logits[(size_t)b * V_ + v];
    g_pen[t] = (g < 0.f) ? g * 1.1f : g / 1.1f;
}
__global__ void __launch_bounds__(256) pen_scatter(const int* __restrict__ ids) {
    const int t = blockIdx.x * 256 + threadIdx.x;
    if (t >= B_ * HIST_) return;
    const int b = t >> 11;
    const int v = ids[t];
    if ((unsigned)v >= (unsigned)V_) return;
    g_logits[(size_t)b * V_ + v] = g_pen[t];     // duplicate v => identical value
}

// ---------------- K2: per-row top-50 + top-p, write output ----------------
__global__ void __launch_bounds__(512, 1) select_kernel(float* __restrict__ out,
                                                        int out_size) {
    __shared__ unsigned int hist[8192];
    __shared__ unsigned long long cand[CAP];
    __shared__ unsigned long long sel[50];
    __shared__ int s_cnt, s_tbin;

    const int b = blockIdx.x, tid = threadIdx.x;
    const float* row = g_logits + (size_t)b * V_;

    for (int i = tid; i < 8192; i += 512) hist[i] = 0u;
    if (tid == 0) s_cnt = 0;
    __syncthreads();

    for (int i = tid; i < V_; i += 512) {
        const unsigned u = __float_as_uint(row[i]);
        const unsigned key = (u & 0x80000000u) ? ~u : (u | 0x80000000u);
        atomicAdd(&hist[key >> 19], 1u);
    }
    __syncthreads();

    if (tid == 0) {
        unsigned cum = 0;
        int t = 0;
        for (int bin = 8191; bin >= 0; bin--) {
            cum += hist[bin];
            if (cum >= 50u) { t = bin; break; }
        }
        s_tbin = t;
    }
    __syncthreads();

    const unsigned tkey = ((unsigned)s_tbin) << 19;
    for (int i = tid; i < V_; i += 512) {
        const unsigned u = __float_as_uint(row[i]);
        const unsigned key = (u & 0x80000000u) ? ~u : (u | 0x80000000u);
        if (key >= tkey) {
            const int pos = atomicAdd(&s_cnt, 1);
            if (pos < CAP)
                cand[pos] = ((unsigned long long)key << 32) | (unsigned)(0xffffffffu - i);
        }
    }
    __syncthreads();
    const int cnt = (s_cnt < CAP) ? s_cnt : CAP;

    // warp 0: extract top-50 in order (desc value, asc index via packed key)
    if (tid < 32) {
        for (int r = 0; r < 50; r++) {
            unsigned long long best = 0ull;
            int bidx = -1;
            for (int i = tid; i < cnt; i += 32)
                if (cand[i] > best) { best = cand[i]; bidx = i; }
#pragma unroll
            for (int off = 16; off >= 1; off >>= 1) {
                const unsigned long long ob = __shfl_xor_sync(0xffffffffu, best, off);
                const int oi = __shfl_xor_sync(0xffffffffu, bidx, off);
                if (ob > best) { best = ob; bidx = oi; }
            }
            if (tid == 0 && bidx >= 0) { sel[r] = best; cand[bidx] = 0ull; }
            __syncwarp();
        }
    }
    __syncthreads();

    if (tid == 0) {
        float vals[50];
        int   tok[50];
        for (int i = 0; i < 50; i++) {
            const unsigned long long k64 = sel[i];
            const unsigned key = (unsigned)(k64 >> 32);
            vals[i] = (key & 0x80000000u) ? __uint_as_float(key ^ 0x80000000u)
                                          : __uint_as_float(~key);
            tok[i] = (int)(0xffffffffu - (unsigned)(k64 & 0xffffffffu));
        }
        // softmax over top-50 (temperature = 1)
        const float m = vals[0];
        float e[50], ssum = 0.f;
        for (int i = 0; i < 50; i++) { e[i] = expf(vals[i] - m); ssum += e[i]; }
        float cum = 0.f, filt[50];
        for (int i = 0; i < 50; i++) {
            cum += e[i] / ssum;
            const bool keep = (cum < 0.8f) || (i < 5);
            filt[i] = keep ? vals[i] : -1000.0f;
        }
        float m2 = filt[0];
        for (int i = 1; i < 50; i++) m2 = fmaxf(m2, filt[i]);
        float s2 = 0.f;
        for (int i = 0; i < 50; i++) s2 += expf(filt[i] - m2);
        const int toff = out_size >> 1;          // probs first, tokens second
        for (int i = 0; i < 50; i++) {
            out[b * 50 + i] = expf(filt[i] - m2) / s2;
            out[toff + b * 50 + i] = (float)tok[i];
        }
    }
}

// ---------------- launch ----------------
extern "C" void kernel_launch(void* const* d_in, const int* in_sizes, int n_in,
                              void* d_out, int out_size) {
    const int*   ids   = (const int*)d_in[0];
    const float* hs    = (const float*)d_in[1];
    const float* gamma = (const float*)d_in[2];
    const float* beta  = (const float*)d_in[3];
    const float* Wm    = (const float*)d_in[4];

    ln_kernel<<<B_, 256>>>(hs, gamma, beta);
    gemm_kernel<<<V_ / VTILE, 512>>>(Wm);
    pen_gather<<<(B_ * HIST_) / 256, 256>>>(ids);
    pen_scatter<<<(B_ * HIST_) / 256, 256>>>(ids);
    select_kernel<<<B_, 512>>>((float*)d_out, out_size);
}